// round 8
// baseline (speedup 1.0000x reference)
#include <cuda_runtime.h>
#include <cstdint>

#define BATCH 8
#define NVAL  261888
#define PRE   6000
#define CAP   8192
#define CAPW  3072
#define PROP  1000
#define W     2048         // NMS window (exact top-W sorted)
#define MWORDS 64          // matrix row words (W/32)
#define SPEC  16           // speculative picks per round
#define FULLM 0xFFFFFFFFu

// ---------------- scratch (static device globals; no allocation) ----------------
__device__ unsigned           g_u[BATCH * NVAL];
__device__ unsigned           g_hist1[BATCH * 65536];
__device__ unsigned           g_hist2[BATCH * 65536];
__device__ unsigned           g_b1w[BATCH];      // coarse bin for rank W
__device__ unsigned           g_abovew[BATCH];   // count strictly above that bin
__device__ unsigned           g_b1p[BATCH];      // coarse bin for rank PRE
__device__ unsigned           g_tw[BATCH];       // exact 32-bit rank-W threshold
__device__ int                g_candcnt[BATCH];
__device__ int                g_topcnt[BATCH];
__device__ unsigned long long g_cand[BATCH * CAP];
__device__ unsigned long long g_top[BATCH * CAPW];
__device__ unsigned long long g_win[BATCH * W];      // sorted top-W keys
__device__ float              g_winbox[BATCH * W * 4];
__device__ unsigned           g_walive[BATCH * 64];
__device__ unsigned           g_mat[(size_t)BATCH * W * MWORDS];   // 4 MB
__device__ float              g_fbb[BATCH * CAP * 4];              // fallback boxes

__device__ __forceinline__ unsigned flip_f(float f) {
    unsigned b = __float_as_uint(f);
    unsigned mask = (unsigned)((int)b >> 31) | 0x80000000u;
    return b ^ mask;
}
__device__ __forceinline__ float unflip_f(unsigned u) {
    unsigned mask = (u >> 31) ? 0x80000000u : 0xFFFFFFFFu;
    return __uint_as_float(u ^ mask);
}

__device__ __forceinline__ float4 compute_box(const float* __restrict__ bbox,
                                              const float* __restrict__ anchors,
                                              int b, int idx) {
    int base = (b * NVAL + idx) * 4;
    float ay1 = anchors[base + 0];
    float ax1 = anchors[base + 1];
    float ay2 = anchors[base + 2];
    float ax2 = anchors[base + 3];
    float d0 = bbox[base + 0] * 0.1f;
    float d1 = bbox[base + 1] * 0.1f;
    float d2 = bbox[base + 2] * 0.2f;
    float d3 = bbox[base + 3] * 0.2f;
    float h = ay2 - ay1;
    float w = ax2 - ax1;
    float cy = ay1 + 0.5f * h;
    float cx = ax1 + 0.5f * w;
    cy = cy + d0 * h;
    cx = cx + d1 * w;
    h = h * expf(d2);
    w = w * expf(d3);
    float y1 = cy - 0.5f * h;
    float x1 = cx - 0.5f * w;
    float y2 = y1 + h;
    float x2 = x1 + w;
    return make_float4(fminf(fmaxf(y1, 0.f), 1.f),
                       fminf(fmaxf(x1, 0.f), 1.f),
                       fminf(fmaxf(y2, 0.f), 1.f),
                       fminf(fmaxf(x2, 0.f), 1.f));
}

// exact reference-order IoU >= 0.7 test (fallback)
__device__ __forceinline__ bool iou_ge07(float4 a, float fa, float4 c) {
    float yy1 = fmaxf(a.x, c.x);
    float xx1 = fmaxf(a.y, c.y);
    float yy2 = fminf(a.z, c.z);
    float xx2 = fminf(a.w, c.w);
    float inter = fmaxf(yy2 - yy1, 0.f) * fmaxf(xx2 - xx1, 0.f);
    float ca = (c.z - c.x) * (c.w - c.y);
    float u = ((fa + ca) - inter) + 1e-8f;
    return inter / u >= 0.7f;
}

__device__ __forceinline__ unsigned long long mk_key(unsigned u, unsigned n) {
    return ((unsigned long long)u << 18) | (unsigned long long)(0x3FFFFu - n);
}

// ---------------- K0: zero scratch ----------------
__global__ void k_zero() {
    int total = BATCH * 65536;
    for (int i = blockIdx.x * blockDim.x + threadIdx.x; i < total;
         i += gridDim.x * blockDim.x) {
        g_hist1[i] = 0;
        g_hist2[i] = 0;
    }
    int gid = blockIdx.x * blockDim.x + threadIdx.x;
    if (gid < BATCH) { g_candcnt[gid] = 0; g_topcnt[gid] = 0; }
    for (int i = gid; i < BATCH * W; i += gridDim.x * blockDim.x)
        g_win[i] = 0ULL;
}

// ---------------- K1: flip scores, hist of high 16 bits ----------------
__global__ void k_score_hist(const float* __restrict__ probs) {
    int b = blockIdx.y;
    const float2* p2 = (const float2*)probs;
    for (int n = blockIdx.x * blockDim.x + threadIdx.x; n < NVAL;
         n += gridDim.x * blockDim.x) {
        float s = p2[b * NVAL + n].y;
        unsigned u = flip_f(s);
        g_u[b * NVAL + n] = u;
        atomicAdd(&g_hist1[b * 65536 + (u >> 16)], 1u);
    }
}

// ---------------- K2: coarse bins for rank W and rank PRE ----------------
__global__ void k_findbins() {
    __shared__ unsigned part[256];
    __shared__ unsigned chw[256], chp[256];
    __shared__ int s_cw, s_cp;
    __shared__ unsigned s_aw, s_ap;
    int b = blockIdx.x;
    const unsigned* hist = g_hist1 + b * 65536;
    unsigned s = 0;
    int base = threadIdx.x * 256;
    for (int i = 0; i < 256; ++i) s += hist[base + i];
    part[threadIdx.x] = s;
    __syncthreads();
    if (threadIdx.x == 0) {
        unsigned acc = 0;
        int cw = -1, cp = -1;
        unsigned aw = 0, ap = 0;
        for (int t = 255; t >= 0; --t) {
            unsigned pt = part[t];
            if (cw < 0 && acc + pt >= (unsigned)W)   { cw = t; aw = acc; }
            if (cp < 0 && acc + pt >= (unsigned)PRE) { cp = t; ap = acc; }
            acc += pt;
            if (cp >= 0) break;
        }
        if (cw < 0) cw = 0;
        if (cp < 0) cp = 0;
        s_cw = cw; s_cp = cp; s_aw = aw; s_ap = ap;
    }
    __syncthreads();
    chw[threadIdx.x] = hist[s_cw * 256 + threadIdx.x];
    chp[threadIdx.x] = hist[s_cp * 256 + threadIdx.x];
    __syncthreads();
    if (threadIdx.x == 0) {
        unsigned acc = s_aw;
        for (int i = 255; i >= 0; --i) {
            unsigned h = chw[i];
            if (acc + h >= (unsigned)W) {
                g_b1w[b] = (unsigned)(s_cw * 256 + i);
                g_abovew[b] = acc;
                break;
            }
            acc += h;
        }
        acc = s_ap;
        for (int i = 255; i >= 0; --i) {
            unsigned h = chp[i];
            if (acc + h >= (unsigned)PRE) {
                g_b1p[b] = (unsigned)(s_cp * 256 + i);
                break;
            }
            acc += h;
        }
    }
}

// ---------------- K3: vectorized compact (u >= coarse PRE threshold) ----------
__global__ void k_compact() {
    int b = blockIdx.y;
    unsigned T = g_b1p[b] << 16;
    int lane = threadIdx.x & 31;
    int gid = blockIdx.x * blockDim.x + threadIdx.x;
    int stride = gridDim.x * blockDim.x;
    const uint4* u4 = (const uint4*)(g_u + b * NVAL);
    const int n4 = NVAL / 4;
    int iters = (n4 + stride - 1) / stride;
    for (int it = 0; it < iters; ++it) {
        int i = gid + it * stride;
        uint4 v = make_uint4(0, 0, 0, 0);
        int c = 0;
        bool inb = (i < n4);
        if (inb) {
            v = u4[i];
            c = (v.x >= T) + (v.y >= T) + (v.z >= T) + (v.w >= T);
        }
        // warp inclusive scan of c
        int incl = c;
        #pragma unroll
        for (int off = 1; off < 32; off <<= 1) {
            int t = __shfl_up_sync(FULLM, incl, off);
            if (lane >= off) incl += t;
        }
        int total = __shfl_sync(FULLM, incl, 31);
        if (total == 0) continue;
        int basepos = 0;
        if (lane == 31) basepos = atomicAdd(&g_candcnt[b], total);
        basepos = __shfl_sync(FULLM, basepos, 31);
        if (inb && c) {
            int pos = basepos + incl - c;
            unsigned n0 = (unsigned)(i * 4);
            if (v.x >= T) { if (pos < CAP) g_cand[b * CAP + pos] = mk_key(v.x, n0 + 0); ++pos; }
            if (v.y >= T) { if (pos < CAP) g_cand[b * CAP + pos] = mk_key(v.y, n0 + 1); ++pos; }
            if (v.z >= T) { if (pos < CAP) g_cand[b * CAP + pos] = mk_key(v.z, n0 + 2); ++pos; }
            if (v.w >= T) { if (pos < CAP) g_cand[b * CAP + pos] = mk_key(v.w, n0 + 3); ++pos; }
        }
    }
}

// ---------------- K4: second-level hist over candidates (rank-W bin) ----------
__global__ void k_hist2c() {
    int b = blockIdx.y;
    int cnt = g_candcnt[b];
    if (cnt > CAP) cnt = CAP;
    unsigned b1 = g_b1w[b];
    for (int i = blockIdx.x * blockDim.x + threadIdx.x; i < cnt;
         i += gridDim.x * blockDim.x) {
        unsigned u = (unsigned)(g_cand[b * CAP + i] >> 18);
        if ((u >> 16) == b1)
            atomicAdd(&g_hist2[b * 65536 + (u & 0xFFFFu)], 1u);
    }
}

// ---------------- K5: exact rank-W threshold ----------------
__global__ void k_findbin2() {
    __shared__ unsigned part[256];
    __shared__ unsigned ch[256];
    __shared__ int s_c;
    __shared__ unsigned s_a;
    int b = blockIdx.x;
    const unsigned* hist = g_hist2 + b * 65536;
    unsigned K = (unsigned)W - g_abovew[b];
    unsigned s = 0;
    int base = threadIdx.x * 256;
    for (int i = 0; i < 256; ++i) s += hist[base + i];
    part[threadIdx.x] = s;
    __syncthreads();
    if (threadIdx.x == 0) {
        unsigned acc = 0;
        int c = 0; unsigned a = 0;
        for (int t = 255; t >= 0; --t) {
            unsigned pt = part[t];
            if (acc + pt >= K) { c = t; a = acc; break; }
            acc += pt;
        }
        s_c = c; s_a = a;
    }
    __syncthreads();
    ch[threadIdx.x] = hist[s_c * 256 + threadIdx.x];
    __syncthreads();
    if (threadIdx.x == 0) {
        unsigned acc = s_a;
        unsigned b2 = 0;
        for (int i = 255; i >= 0; --i) {
            unsigned h = ch[i];
            if (acc + h >= K) { b2 = (unsigned)(s_c * 256 + i); break; }
            acc += h;
        }
        g_tw[b] = (g_b1w[b] << 16) | b2;
    }
}

// ---------------- K6: compact top set (u >= exact rank-W threshold) ----------
__global__ void k_ctop() {
    int b = blockIdx.y;
    unsigned long long Tk = ((unsigned long long)g_tw[b]) << 18;
    int cnt = g_candcnt[b];
    if (cnt > CAP) cnt = CAP;
    int lane = threadIdx.x & 31;
    int gid = blockIdx.x * blockDim.x + threadIdx.x;
    int stride = gridDim.x * blockDim.x;
    int iters = (cnt + stride - 1) / stride;
    for (int it = 0; it < iters; ++it) {
        int i = gid + it * stride;
        unsigned long long key = 0;
        bool pass = false;
        if (i < cnt) {
            key = g_cand[b * CAP + i];
            pass = (key >= Tk);
        }
        unsigned bal = __ballot_sync(FULLM, pass);
        if (!bal) continue;
        int leader = __ffs(bal) - 1;
        int basepos = 0;
        if (lane == leader) basepos = atomicAdd(&g_topcnt[b], __popc(bal));
        basepos = __shfl_sync(FULLM, basepos, leader);
        if (pass) {
            int pos = basepos + __popc(bal & ((1u << lane) - 1u));
            if (pos < CAPW) g_top[b * CAPW + pos] = key;
        }
    }
}

// ---------------- K7: counting-rank sort of top set into window ----------------
__global__ void k_rank() {
    __shared__ unsigned long long tile[1024];
    int b = blockIdx.y;
    int tc = g_topcnt[b];
    if (tc > CAPW) return;   // window disabled -> fallback handles everything
    int i = blockIdx.x * blockDim.x + threadIdx.x;
    unsigned long long key = (i < tc) ? g_top[b * CAPW + i] : 0ULL;
    int rank = 0;
    for (int t0 = 0; t0 < tc; t0 += 1024) {
        int j = t0 + threadIdx.x;
        tile[threadIdx.x] = (j < tc) ? g_top[b * CAPW + j] : 0ULL;
        __syncthreads();
        int lim = tc - t0; if (lim > 1024) lim = 1024;
        for (int j2 = 0; j2 < lim; ++j2)
            rank += (tile[j2] > key);
        __syncthreads();
    }
    if (i < tc && rank < W) g_win[b * W + rank] = key;
}

// ---------------- K8: window boxes + alive bits ----------------
__global__ void k_winbox(const float* __restrict__ bbox,
                         const float* __restrict__ anchors) {
    int b = blockIdx.y;
    int t = blockIdx.x * blockDim.x + threadIdx.x;
    unsigned long long key = g_win[b * W + t];
    float4 box = make_float4(0.f, 0.f, 0.f, 0.f);
    bool live = false;
    if (key != 0ULL) {
        unsigned u = (unsigned)(key >> 18);
        unsigned idx = 0x3FFFFu - (unsigned)(key & 0x3FFFFu);
        if (idx < (unsigned)NVAL) {
            live = (unflip_f(u) >= 0.5f);
            box = compute_box(bbox, anchors, b, (int)idx);
        }
    }
    ((float4*)g_winbox)[b * W + t] = box;
    unsigned bal = __ballot_sync(FULLM, live);
    if ((threadIdx.x & 31) == 0) g_walive[b * 64 + (t >> 5)] = bal;
}

// ---------------- K9: windowed suppression matrix build ----------------
__global__ void k_build() {
    int bx = blockIdx.x, by = blockIdx.y, b = blockIdx.z;
    if (bx * 64 + 64 <= by * 128) return;   // tile entirely j < i
    __shared__ float4 cb[64];
    __shared__ float  ca[64];
    int t = threadIdx.x;
    int j0 = bx * 64;
    const float4* boxes4 = (const float4*)g_winbox;
    if (t < 64) {
        float4 a = boxes4[b * W + j0 + t];
        cb[t] = a;
        ca[t] = (a.z - a.x) * (a.w - a.y);
    }
    __syncthreads();
    int i = by * 128 + t;
    float4 r = boxes4[b * W + i];
    float ra = (r.z - r.x) * (r.w - r.y);
    unsigned w0 = 0, w1 = 0;
    #pragma unroll 8
    for (int jj = 0; jj < 64; ++jj) {
        int j = j0 + jj;
        bool sup = false;
        if (j > i) {
            float4 c = cb[jj];
            float yy1 = fmaxf(r.x, c.x);
            float xx1 = fmaxf(r.y, c.y);
            float yy2 = fminf(r.z, c.z);
            float xx2 = fminf(r.w, c.w);
            float inter = fmaxf(yy2 - yy1, 0.f) * fmaxf(xx2 - xx1, 0.f);
            float u = ((ra + ca[jj]) - inter) + 1e-8f;
            if (inter >= 0.700007f * u)       sup = true;
            else if (inter <= 0.699993f * u)  sup = false;
            else                              sup = (inter / u >= 0.7f);
        }
        if (jj < 32) w0 |= ((unsigned)sup) << jj;
        else         w1 |= ((unsigned)sup) << (jj - 32);
    }
    uint2* rb = (uint2*)(g_mat + ((size_t)b * W + i) * MWORDS + bx * 2);
    *rb = make_uint2(w0, w1);
}

// ---------------- K10: frontier NMS + self-contained exact fallback ----------
__global__ void k_nms_fast(float* __restrict__ out,
                           const float* __restrict__ bbox,
                           const float* __restrict__ anchors) {
    __shared__ int s_picks[PROP];
    __shared__ unsigned s_alive[CAP / 32];
    int b = blockIdx.x;
    int lane = threadIdx.x;
    const float4* wbox4 = (const float4*)g_winbox;

    for (int t = lane; t < PROP * 4; t += 32) out[b * PROP * 4 + t] = 0.f;

    unsigned a0 = g_walive[b * 64 + lane];
    unsigned a1 = g_walive[b * 64 + 32 + lane];
    const unsigned* mat = g_mat + (size_t)b * W * MWORDS;

    int p = 0;
    while (p < PROP) {
        unsigned bal0 = __ballot_sync(FULLM, a0 != 0u);
        unsigned bal1 = __ballot_sync(FULLM, a1 != 0u);
        if (!bal0 && !bal1) break;

        int F, F2 = -1;
        unsigned bb0 = bal0, bb1 = bal1;
        if (bb0) { F = __ffs(bb0) - 1; bb0 &= bb0 - 1; }
        else     { F = 32 + __ffs(bb1) - 1; bb1 &= bb1 - 1; }
        if (bb0)      F2 = __ffs(bb0) - 1;
        else if (bb1) F2 = 32 + __ffs(bb1) - 1;

        unsigned w0 = __shfl_sync(FULLM, (F < 32) ? a0 : a1, F & 31);
        unsigned w1 = (F2 >= 0)
                      ? __shfl_sync(FULLM, (F2 < 32) ? a0 : a1, F2 & 31) : 0u;

        int cand[SPEC];
        int found = 0;
        unsigned t = w0;
        while (t && found < SPEC) { int bit = __ffs(t) - 1; t &= t - 1;
                                    cand[found++] = F * 32 + bit; }
        t = w1;
        while (t && found < SPEC) { int bit = __ffs(t) - 1; t &= t - 1;
                                    cand[found++] = F2 * 32 + bit; }

        unsigned rw0[SPEC], rw1[SPEC];
        #pragma unroll
        for (int c = 0; c < SPEC; ++c) {
            if (c < found) {
                const unsigned* row = mat + (size_t)cand[c] * MWORDS;
                rw0[c] = row[lane];
                rw1[c] = row[32 + lane];
            } else { rw0[c] = 0; rw1[c] = 0; }
        }

        unsigned fw0[SPEC], fw1[SPEC];
        #pragma unroll
        for (int c = 0; c < SPEC; ++c) {
            fw0[c] = __shfl_sync(FULLM, (F < 32) ? rw0[c] : rw1[c], F & 31);
            fw1[c] = (F2 >= 0)
                     ? __shfl_sync(FULLM, (F2 < 32) ? rw0[c] : rw1[c], F2 & 31) : 0u;
        }

        unsigned u0 = w0, u1 = w1;
        unsigned accmask = 0;
        #pragma unroll
        for (int c = 0; c < SPEC; ++c) {
            if (c >= found || p >= PROP) continue;
            int pos = cand[c];
            bool inF = ((pos >> 5) == F);
            unsigned cw = inF ? u0 : u1;
            if ((cw >> (pos & 31)) & 1u) {
                accmask |= 1u << c;
                if (lane == 0) s_picks[p] = pos;
                ++p;
                u0 &= ~fw0[c];
                u1 &= ~fw1[c];
                if (inF) u0 &= ~(1u << (pos & 31));
                else     u1 &= ~(1u << (pos & 31));
            }
        }

        #pragma unroll
        for (int c = 0; c < SPEC; ++c) {
            if (accmask & (1u << c)) {
                a0 &= ~rw0[c];
                a1 &= ~rw1[c];
                int pos = cand[c];
                int wd = pos >> 5;
                if (lane == (wd & 31)) {
                    if (wd < 32) a0 &= ~(1u << (pos & 31));
                    else         a1 &= ~(1u << (pos & 31));
                }
            }
        }
    }

    int p_fast = p;

    // ============ exact self-contained fallback (dead in practice) ============
    if (p < PROP) {
        int cnt = g_candcnt[b];
        if (cnt > CAP) cnt = CAP;
        float4* fbb4 = (float4*)g_fbb;

        // boxes for all candidates
        for (int i = lane; i < cnt; i += 32) {
            unsigned long long key = g_cand[b * CAP + i];
            unsigned idx = 0x3FFFFu - (unsigned)(key & 0x3FFFFu);
            fbb4[b * CAP + i] = (idx < (unsigned)NVAL)
                ? compute_box(bbox, anchors, b, (int)idx)
                : make_float4(0.f, 0.f, 0.f, 0.f);
        }
        // exact top-PRE membership by global rank + score threshold
        for (int wd = lane; wd < CAP / 32; wd += 32) s_alive[wd] = 0u;
        __syncwarp();
        for (int i = lane; i < cnt; i += 32) {
            unsigned long long key = g_cand[b * CAP + i];
            int rank = 0;
            for (int j = 0; j < cnt; ++j)
                rank += (g_cand[b * CAP + j] > key);
            bool live = (rank < PRE) &&
                        (unflip_f((unsigned)(key >> 18)) >= 0.5f);
            if (live) atomicOr(&s_alive[i >> 5], 1u << (i & 31));
        }
        __syncwarp();
        // replay fast-path picks
        for (int q = 0; q < p_fast; ++q) {
            float4 pb = wbox4[b * W + s_picks[q]];
            float pa = (pb.z - pb.x) * (pb.w - pb.y);
            for (int i = lane; i < cnt; i += 32) {
                if (s_alive[i >> 5] & (1u << (i & 31))) {
                    if (iou_ge07(pb, pa, fbb4[b * CAP + i]))
                        atomicAnd(&s_alive[i >> 5], ~(1u << (i & 31)));
                }
            }
            __syncwarp();
        }
        // continue exact greedy NMS (argmax key among alive)
        while (p < PROP) {
            unsigned long long bestk = 0ULL;
            int besti = -1;
            for (int i = lane; i < cnt; i += 32) {
                if (s_alive[i >> 5] & (1u << (i & 31))) {
                    unsigned long long k2 = g_cand[b * CAP + i];
                    if (k2 > bestk) { bestk = k2; besti = i; }
                }
            }
            #pragma unroll
            for (int off = 16; off; off >>= 1) {
                unsigned long long ok = __shfl_xor_sync(FULLM, bestk, off);
                int oi = __shfl_xor_sync(FULLM, besti, off);
                if (ok > bestk) { bestk = ok; besti = oi; }
            }
            if (besti < 0) break;
            float4 pb = fbb4[b * CAP + besti];
            if (lane == 0) ((float4*)out)[b * PROP + p] = pb;
            float pa = (pb.z - pb.x) * (pb.w - pb.y);
            for (int i = lane; i < cnt; i += 32) {
                if (s_alive[i >> 5] & (1u << (i & 31))) {
                    if (iou_ge07(pb, pa, fbb4[b * CAP + i]))
                        atomicAnd(&s_alive[i >> 5], ~(1u << (i & 31)));
                }
            }
            __syncwarp();
            ++p;
        }
    }

    // parallel emit of fast-path picks
    __syncwarp();
    float4* out4 = (float4*)out;
    for (int q = lane; q < p_fast; q += 32)
        out4[b * PROP + q] = wbox4[b * W + s_picks[q]];
}

// ---------------- launch ----------------
extern "C" void kernel_launch(void* const* d_in, const int* in_sizes, int n_in,
                              void* d_out, int out_size) {
    const float* probs   = (const float*)d_in[0];
    const float* bbox    = (const float*)d_in[1];
    const float* anchors = (const float*)d_in[2];
    float* out = (float*)d_out;
    (void)in_sizes; (void)n_in; (void)out_size;

    k_zero<<<512, 256>>>();

    dim3 gridN(256, BATCH);
    k_score_hist<<<gridN, 256>>>(probs);
    k_findbins<<<BATCH, 256>>>();
    dim3 gridC(64, BATCH);
    k_compact<<<gridC, 256>>>();
    dim3 gridH(8, BATCH);
    k_hist2c<<<gridH, 256>>>();
    k_findbin2<<<BATCH, 256>>>();
    dim3 gridT(8, BATCH);
    k_ctop<<<gridT, 256>>>();
    dim3 gridR(CAPW / 1024, BATCH);
    k_rank<<<gridR, 1024>>>();
    dim3 gridW(W / 256, BATCH);
    k_winbox<<<gridW, 256>>>(bbox, anchors);
    dim3 gridB(W / 64, W / 128, BATCH);
    k_build<<<gridB, 128>>>();
    k_nms_fast<<<BATCH, 32>>>(out, bbox, anchors);
}

// round 9
// speedup vs baseline: 1.6649x; 1.6649x over previous
#include <cuda_runtime.h>
#include <cstdint>

#define BATCH 8
#define NVAL  261888
#define PRE   6000
#define CAP   8192
#define CAPW  3072
#define PROP  1000
#define W     2048         // NMS window (exact top-W sorted)
#define MWORDS 64          // matrix row words (W/32)
#define SPEC  16           // speculative picks per round
#define FULLM 0xFFFFFFFFu

// ---------------- scratch (static device globals; no allocation) ----------------
__device__ unsigned           g_u[BATCH * NVAL];
__device__ unsigned           g_hist1[BATCH * 65536];
__device__ unsigned           g_hist2[BATCH * 65536];
__device__ unsigned           g_b1w[BATCH];
__device__ unsigned           g_abovew[BATCH];
__device__ unsigned           g_b1p[BATCH];
__device__ unsigned           g_tw[BATCH];
__device__ int                g_candcnt[BATCH];
__device__ int                g_topcnt[BATCH];
__device__ unsigned long long g_cand[BATCH * CAP];
__device__ unsigned long long g_top[BATCH * CAPW];
__device__ unsigned long long g_win[BATCH * W];
__device__ float              g_winbox[BATCH * W * 4];
__device__ unsigned           g_walive[BATCH * 64];
__device__ unsigned           g_mat[(size_t)BATCH * W * MWORDS];   // 4 MB
__device__ float              g_fbb[BATCH * CAP * 4];
__device__ int                g_picks[BATCH * PROP];
__device__ int                g_fbcount[BATCH];
__device__ int                g_fbneed[BATCH];

__device__ __forceinline__ unsigned flip_f(float f) {
    unsigned b = __float_as_uint(f);
    unsigned mask = (unsigned)((int)b >> 31) | 0x80000000u;
    return b ^ mask;
}
__device__ __forceinline__ float unflip_f(unsigned u) {
    unsigned mask = (u >> 31) ? 0x80000000u : 0xFFFFFFFFu;
    return __uint_as_float(u ^ mask);
}

__device__ __forceinline__ float4 compute_box(const float* __restrict__ bbox,
                                              const float* __restrict__ anchors,
                                              int b, int idx) {
    int base = (b * NVAL + idx) * 4;
    float ay1 = anchors[base + 0];
    float ax1 = anchors[base + 1];
    float ay2 = anchors[base + 2];
    float ax2 = anchors[base + 3];
    float d0 = bbox[base + 0] * 0.1f;
    float d1 = bbox[base + 1] * 0.1f;
    float d2 = bbox[base + 2] * 0.2f;
    float d3 = bbox[base + 3] * 0.2f;
    float h = ay2 - ay1;
    float w = ax2 - ax1;
    float cy = ay1 + 0.5f * h;
    float cx = ax1 + 0.5f * w;
    cy = cy + d0 * h;
    cx = cx + d1 * w;
    h = h * expf(d2);
    w = w * expf(d3);
    float y1 = cy - 0.5f * h;
    float x1 = cx - 0.5f * w;
    float y2 = y1 + h;
    float x2 = x1 + w;
    return make_float4(fminf(fmaxf(y1, 0.f), 1.f),
                       fminf(fmaxf(x1, 0.f), 1.f),
                       fminf(fmaxf(y2, 0.f), 1.f),
                       fminf(fmaxf(x2, 0.f), 1.f));
}

__device__ __forceinline__ bool iou_ge07(float4 a, float fa, float4 c) {
    float yy1 = fmaxf(a.x, c.x);
    float xx1 = fmaxf(a.y, c.y);
    float yy2 = fminf(a.z, c.z);
    float xx2 = fminf(a.w, c.w);
    float inter = fmaxf(yy2 - yy1, 0.f) * fmaxf(xx2 - xx1, 0.f);
    float ca = (c.z - c.x) * (c.w - c.y);
    float u = ((fa + ca) - inter) + 1e-8f;
    return inter / u >= 0.7f;
}

__device__ __forceinline__ unsigned long long mk_key(unsigned u, unsigned n) {
    return ((unsigned long long)u << 18) | (unsigned long long)(0x3FFFFu - n);
}

// ---------------- K0: zero scratch ----------------
__global__ void k_zero() {
    int total = BATCH * 65536;
    for (int i = blockIdx.x * blockDim.x + threadIdx.x; i < total;
         i += gridDim.x * blockDim.x) {
        g_hist1[i] = 0;
        g_hist2[i] = 0;
    }
    int gid = blockIdx.x * blockDim.x + threadIdx.x;
    if (gid < BATCH) { g_candcnt[gid] = 0; g_topcnt[gid] = 0; }
    for (int i = gid; i < BATCH * W; i += gridDim.x * blockDim.x)
        g_win[i] = 0ULL;
}

// ---------------- K1: flip scores, hist of high 16 bits ----------------
__global__ void k_score_hist(const float* __restrict__ probs) {
    int b = blockIdx.y;
    const float2* p2 = (const float2*)probs;
    for (int n = blockIdx.x * blockDim.x + threadIdx.x; n < NVAL;
         n += gridDim.x * blockDim.x) {
        float s = p2[b * NVAL + n].y;
        unsigned u = flip_f(s);
        g_u[b * NVAL + n] = u;
        atomicAdd(&g_hist1[b * 65536 + (u >> 16)], 1u);
    }
}

// ---------------- K2: coarse bins for rank W and rank PRE ----------------
__global__ void k_findbins() {
    __shared__ unsigned part[256];
    __shared__ unsigned chw[256], chp[256];
    __shared__ int s_cw, s_cp;
    __shared__ unsigned s_aw, s_ap;
    int b = blockIdx.x;
    const unsigned* hist = g_hist1 + b * 65536;
    unsigned s = 0;
    int base = threadIdx.x * 256;
    for (int i = 0; i < 256; ++i) s += hist[base + i];
    part[threadIdx.x] = s;
    __syncthreads();
    if (threadIdx.x == 0) {
        unsigned acc = 0;
        int cw = -1, cp = -1;
        unsigned aw = 0, ap = 0;
        for (int t = 255; t >= 0; --t) {
            unsigned pt = part[t];
            if (cw < 0 && acc + pt >= (unsigned)W)   { cw = t; aw = acc; }
            if (cp < 0 && acc + pt >= (unsigned)PRE) { cp = t; ap = acc; }
            acc += pt;
            if (cp >= 0) break;
        }
        if (cw < 0) cw = 0;
        if (cp < 0) cp = 0;
        s_cw = cw; s_cp = cp; s_aw = aw; s_ap = ap;
    }
    __syncthreads();
    chw[threadIdx.x] = hist[s_cw * 256 + threadIdx.x];
    chp[threadIdx.x] = hist[s_cp * 256 + threadIdx.x];
    __syncthreads();
    if (threadIdx.x == 0) {
        unsigned acc = s_aw;
        for (int i = 255; i >= 0; --i) {
            unsigned h = chw[i];
            if (acc + h >= (unsigned)W) {
                g_b1w[b] = (unsigned)(s_cw * 256 + i);
                g_abovew[b] = acc;
                break;
            }
            acc += h;
        }
        acc = s_ap;
        for (int i = 255; i >= 0; --i) {
            unsigned h = chp[i];
            if (acc + h >= (unsigned)PRE) {
                g_b1p[b] = (unsigned)(s_cp * 256 + i);
                break;
            }
            acc += h;
        }
    }
}

// ---------------- K3: vectorized compact (u >= coarse PRE threshold) ----------
__global__ void k_compact() {
    int b = blockIdx.y;
    unsigned T = g_b1p[b] << 16;
    int lane = threadIdx.x & 31;
    int gid = blockIdx.x * blockDim.x + threadIdx.x;
    int stride = gridDim.x * blockDim.x;
    const uint4* u4 = (const uint4*)(g_u + b * NVAL);
    const int n4 = NVAL / 4;
    int iters = (n4 + stride - 1) / stride;
    for (int it = 0; it < iters; ++it) {
        int i = gid + it * stride;
        uint4 v = make_uint4(0, 0, 0, 0);
        int c = 0;
        bool inb = (i < n4);
        if (inb) {
            v = u4[i];
            c = (v.x >= T) + (v.y >= T) + (v.z >= T) + (v.w >= T);
        }
        int incl = c;
        #pragma unroll
        for (int off = 1; off < 32; off <<= 1) {
            int t = __shfl_up_sync(FULLM, incl, off);
            if (lane >= off) incl += t;
        }
        int total = __shfl_sync(FULLM, incl, 31);
        if (total == 0) continue;
        int basepos = 0;
        if (lane == 31) basepos = atomicAdd(&g_candcnt[b], total);
        basepos = __shfl_sync(FULLM, basepos, 31);
        if (inb && c) {
            int pos = basepos + incl - c;
            unsigned n0 = (unsigned)(i * 4);
            if (v.x >= T) { if (pos < CAP) g_cand[b * CAP + pos] = mk_key(v.x, n0 + 0); ++pos; }
            if (v.y >= T) { if (pos < CAP) g_cand[b * CAP + pos] = mk_key(v.y, n0 + 1); ++pos; }
            if (v.z >= T) { if (pos < CAP) g_cand[b * CAP + pos] = mk_key(v.z, n0 + 2); ++pos; }
            if (v.w >= T) { if (pos < CAP) g_cand[b * CAP + pos] = mk_key(v.w, n0 + 3); ++pos; }
        }
    }
}

// ---------------- K4: second-level hist over candidates (rank-W bin) ----------
__global__ void k_hist2c() {
    int b = blockIdx.y;
    int cnt = g_candcnt[b];
    if (cnt > CAP) cnt = CAP;
    unsigned b1 = g_b1w[b];
    for (int i = blockIdx.x * blockDim.x + threadIdx.x; i < cnt;
         i += gridDim.x * blockDim.x) {
        unsigned u = (unsigned)(g_cand[b * CAP + i] >> 18);
        if ((u >> 16) == b1)
            atomicAdd(&g_hist2[b * 65536 + (u & 0xFFFFu)], 1u);
    }
}

// ---------------- K5: exact rank-W threshold ----------------
__global__ void k_findbin2() {
    __shared__ unsigned part[256];
    __shared__ unsigned ch[256];
    __shared__ int s_c;
    __shared__ unsigned s_a;
    int b = blockIdx.x;
    const unsigned* hist = g_hist2 + b * 65536;
    unsigned K = (unsigned)W - g_abovew[b];
    unsigned s = 0;
    int base = threadIdx.x * 256;
    for (int i = 0; i < 256; ++i) s += hist[base + i];
    part[threadIdx.x] = s;
    __syncthreads();
    if (threadIdx.x == 0) {
        unsigned acc = 0;
        int c = 0; unsigned a = 0;
        for (int t = 255; t >= 0; --t) {
            unsigned pt = part[t];
            if (acc + pt >= K) { c = t; a = acc; break; }
            acc += pt;
        }
        s_c = c; s_a = a;
    }
    __syncthreads();
    ch[threadIdx.x] = hist[s_c * 256 + threadIdx.x];
    __syncthreads();
    if (threadIdx.x == 0) {
        unsigned acc = s_a;
        unsigned b2 = 0;
        for (int i = 255; i >= 0; --i) {
            unsigned h = ch[i];
            if (acc + h >= K) { b2 = (unsigned)(s_c * 256 + i); break; }
            acc += h;
        }
        g_tw[b] = (g_b1w[b] << 16) | b2;
    }
}

// ---------------- K6: compact top set (u >= exact rank-W threshold) ----------
__global__ void k_ctop() {
    int b = blockIdx.y;
    unsigned long long Tk = ((unsigned long long)g_tw[b]) << 18;
    int cnt = g_candcnt[b];
    if (cnt > CAP) cnt = CAP;
    int lane = threadIdx.x & 31;
    int gid = blockIdx.x * blockDim.x + threadIdx.x;
    int stride = gridDim.x * blockDim.x;
    int iters = (cnt + stride - 1) / stride;
    for (int it = 0; it < iters; ++it) {
        int i = gid + it * stride;
        unsigned long long key = 0;
        bool pass = false;
        if (i < cnt) {
            key = g_cand[b * CAP + i];
            pass = (key >= Tk);
        }
        unsigned bal = __ballot_sync(FULLM, pass);
        if (!bal) continue;
        int leader = __ffs(bal) - 1;
        int basepos = 0;
        if (lane == leader) basepos = atomicAdd(&g_topcnt[b], __popc(bal));
        basepos = __shfl_sync(FULLM, basepos, leader);
        if (pass) {
            int pos = basepos + __popc(bal & ((1u << lane) - 1u));
            if (pos < CAPW) g_top[b * CAPW + pos] = key;
        }
    }
}

// ---------------- K7: counting-rank sort (256-thr blocks, wide grid) ----------
__global__ void k_rank() {
    __shared__ unsigned long long tile[256];
    int b = blockIdx.y;
    int tc = g_topcnt[b];
    if (tc > CAPW) return;   // window disabled -> fallback handles everything
    int i = blockIdx.x * blockDim.x + threadIdx.x;
    unsigned long long key = (i < tc) ? g_top[b * CAPW + i] : 0ULL;
    int rank = 0;
    for (int t0 = 0; t0 < tc; t0 += 256) {
        int j = t0 + threadIdx.x;
        tile[threadIdx.x] = (j < tc) ? g_top[b * CAPW + j] : 0ULL;
        __syncthreads();
        int lim = tc - t0; if (lim > 256) lim = 256;
        #pragma unroll 4
        for (int j2 = 0; j2 < lim; ++j2)
            rank += (tile[j2] > key);
        __syncthreads();
    }
    if (i < tc && rank < W) g_win[b * W + rank] = key;
}

// ---------------- K8: window boxes + alive bits ----------------
__global__ void k_winbox(const float* __restrict__ bbox,
                         const float* __restrict__ anchors) {
    int b = blockIdx.y;
    int t = blockIdx.x * blockDim.x + threadIdx.x;
    unsigned long long key = g_win[b * W + t];
    float4 box = make_float4(0.f, 0.f, 0.f, 0.f);
    bool live = false;
    if (key != 0ULL) {
        unsigned u = (unsigned)(key >> 18);
        unsigned idx = 0x3FFFFu - (unsigned)(key & 0x3FFFFu);
        if (idx < (unsigned)NVAL) {
            live = (unflip_f(u) >= 0.5f);
            box = compute_box(bbox, anchors, b, (int)idx);
        }
    }
    ((float4*)g_winbox)[b * W + t] = box;
    unsigned bal = __ballot_sync(FULLM, live);
    if ((threadIdx.x & 31) == 0) g_walive[b * 64 + (t >> 5)] = bal;
}

// ---------------- K9: windowed suppression matrix build ----------------
__global__ void k_build() {
    int bx = blockIdx.x, by = blockIdx.y, b = blockIdx.z;
    if (bx * 64 + 64 <= by * 128) return;
    __shared__ float4 cb[64];
    __shared__ float  ca[64];
    int t = threadIdx.x;
    int j0 = bx * 64;
    const float4* boxes4 = (const float4*)g_winbox;
    if (t < 64) {
        float4 a = boxes4[b * W + j0 + t];
        cb[t] = a;
        ca[t] = (a.z - a.x) * (a.w - a.y);
    }
    __syncthreads();
    int i = by * 128 + t;
    float4 r = boxes4[b * W + i];
    float ra = (r.z - r.x) * (r.w - r.y);
    unsigned w0 = 0, w1 = 0;
    #pragma unroll 8
    for (int jj = 0; jj < 64; ++jj) {
        int j = j0 + jj;
        bool sup = false;
        if (j > i) {
            float4 c = cb[jj];
            float yy1 = fmaxf(r.x, c.x);
            float xx1 = fmaxf(r.y, c.y);
            float yy2 = fminf(r.z, c.z);
            float xx2 = fminf(r.w, c.w);
            float inter = fmaxf(yy2 - yy1, 0.f) * fmaxf(xx2 - xx1, 0.f);
            float u = ((ra + ca[jj]) - inter) + 1e-8f;
            if (inter >= 0.700007f * u)       sup = true;
            else if (inter <= 0.699993f * u)  sup = false;
            else                              sup = (inter / u >= 0.7f);
        }
        if (jj < 32) w0 |= ((unsigned)sup) << jj;
        else         w1 |= ((unsigned)sup) << (jj - 32);
    }
    uint2* rb = (uint2*)(g_mat + ((size_t)b * W + i) * MWORDS + bx * 2);
    *rb = make_uint2(w0, w1);
}

// ---------------- K10: lean frontier NMS (one warp per batch) ----------------
__global__ void k_nms_fast(float* __restrict__ out) {
    __shared__ int s_picks[PROP];
    __shared__ unsigned s_rows[SPEC][64];
    int b = blockIdx.x;
    int lane = threadIdx.x;
    const float4* wbox4 = (const float4*)g_winbox;

    for (int t = lane; t < PROP * 4; t += 32) out[b * PROP * 4 + t] = 0.f;

    unsigned a0 = g_walive[b * 64 + lane];
    unsigned a1 = g_walive[b * 64 + 32 + lane];
    const unsigned* mat = g_mat + (size_t)b * W * MWORDS;

    int p = 0;
    while (p < PROP) {
        unsigned bal0 = __ballot_sync(FULLM, a0 != 0u);
        unsigned bal1 = __ballot_sync(FULLM, a1 != 0u);
        if (!bal0 && !bal1) break;

        int F, F2 = -1;
        unsigned bb0 = bal0, bb1 = bal1;
        if (bb0) { F = __ffs(bb0) - 1; bb0 &= bb0 - 1; }
        else     { F = 32 + __ffs(bb1) - 1; bb1 &= bb1 - 1; }
        if (bb0)      F2 = __ffs(bb0) - 1;
        else if (bb1) F2 = 32 + __ffs(bb1) - 1;

        unsigned w0 = __shfl_sync(FULLM, (F < 32) ? a0 : a1, F & 31);
        unsigned w1 = (F2 >= 0)
                      ? __shfl_sync(FULLM, (F2 < 32) ? a0 : a1, F2 & 31) : 0u;

        int cand[SPEC];
        int found = 0;
        unsigned t = w0;
        while (t && found < SPEC) { int bit = __ffs(t) - 1; t &= t - 1;
                                    cand[found++] = F * 32 + bit; }
        t = w1;
        while (t && found < SPEC) { int bit = __ffs(t) - 1; t &= t - 1;
                                    cand[found++] = F2 * 32 + bit; }

        // stage candidate rows in shared (no register arrays, no shfl fan-out)
        #pragma unroll
        for (int c = 0; c < SPEC; ++c) {
            if (c < found) {
                const unsigned* row = mat + (size_t)cand[c] * MWORDS;
                s_rows[c][lane]      = row[lane];
                s_rows[c][32 + lane] = row[32 + lane];
            }
        }
        __syncwarp();

        // prefetch frontier words (broadcast LDS, independent)
        unsigned fw0[SPEC], fw1[SPEC];
        #pragma unroll
        for (int c = 0; c < SPEC; ++c) {
            fw0[c] = (c < found) ? s_rows[c][F] : 0u;
            fw1[c] = (c < found && F2 >= 0) ? s_rows[c][F2] : 0u;
        }

        unsigned u0 = w0, u1 = w1;
        unsigned accmask = 0;
        #pragma unroll
        for (int c = 0; c < SPEC; ++c) {
            if (c >= found || p >= PROP) continue;
            int pos = cand[c];
            bool inF = ((pos >> 5) == F);
            unsigned cw = inF ? u0 : u1;
            if ((cw >> (pos & 31)) & 1u) {
                accmask |= 1u << c;
                if (lane == 0) s_picks[p] = pos;
                ++p;
                u0 &= ~fw0[c];
                u1 &= ~fw1[c];
                if (inF) u0 &= ~(1u << (pos & 31));
                else     u1 &= ~(1u << (pos & 31));
            }
        }

        #pragma unroll
        for (int c = 0; c < SPEC; ++c) {
            if (accmask & (1u << c)) {
                a0 &= ~s_rows[c][lane];
                a1 &= ~s_rows[c][32 + lane];
                int pos = cand[c];
                int wd = pos >> 5;
                if (lane == (wd & 31)) {
                    if (wd < 32) a0 &= ~(1u << (pos & 31));
                    else         a1 &= ~(1u << (pos & 31));
                }
            }
        }
        __syncwarp();
    }

    // emit fast-path picks + record state for the (normally dead) fallback
    float4* out4 = (float4*)out;
    for (int q = lane; q < p; q += 32) {
        int pos = s_picks[q];
        out4[b * PROP + q] = wbox4[b * W + pos];
        g_picks[b * PROP + q] = pos;
    }
    if (lane == 0) {
        g_fbcount[b] = p;
        g_fbneed[b] = (p < PROP) ? 1 : 0;
    }
}

// ---------------- K11: exact fallback kernel (early-exits when unneeded) ------
__global__ void k_nms_exact(float* __restrict__ out,
                            const float* __restrict__ bbox,
                            const float* __restrict__ anchors) {
    __shared__ unsigned s_alive[CAP / 32];
    int b = blockIdx.x;
    if (!g_fbneed[b]) return;
    int lane = threadIdx.x;
    const float4* wbox4 = (const float4*)g_winbox;
    int p_fast = g_fbcount[b];
    int p = p_fast;

    int cnt = g_candcnt[b];
    if (cnt > CAP) cnt = CAP;
    float4* fbb4 = (float4*)g_fbb;

    for (int i = lane; i < cnt; i += 32) {
        unsigned long long key = g_cand[b * CAP + i];
        unsigned idx = 0x3FFFFu - (unsigned)(key & 0x3FFFFu);
        fbb4[b * CAP + i] = (idx < (unsigned)NVAL)
            ? compute_box(bbox, anchors, b, (int)idx)
            : make_float4(0.f, 0.f, 0.f, 0.f);
    }
    for (int wd = lane; wd < CAP / 32; wd += 32) s_alive[wd] = 0u;
    __syncwarp();
    for (int i = lane; i < cnt; i += 32) {
        unsigned long long key = g_cand[b * CAP + i];
        int rank = 0;
        for (int j = 0; j < cnt; ++j)
            rank += (g_cand[b * CAP + j] > key);
        bool live = (rank < PRE) &&
                    (unflip_f((unsigned)(key >> 18)) >= 0.5f);
        if (live) atomicOr(&s_alive[i >> 5], 1u << (i & 31));
    }
    __syncwarp();
    for (int q = 0; q < p_fast; ++q) {
        float4 pb = wbox4[b * W + g_picks[b * PROP + q]];
        float pa = (pb.z - pb.x) * (pb.w - pb.y);
        for (int i = lane; i < cnt; i += 32) {
            if (s_alive[i >> 5] & (1u << (i & 31))) {
                if (iou_ge07(pb, pa, fbb4[b * CAP + i]))
                    atomicAnd(&s_alive[i >> 5], ~(1u << (i & 31)));
            }
        }
        __syncwarp();
    }
    while (p < PROP) {
        unsigned long long bestk = 0ULL;
        int besti = -1;
        for (int i = lane; i < cnt; i += 32) {
            if (s_alive[i >> 5] & (1u << (i & 31))) {
                unsigned long long k2 = g_cand[b * CAP + i];
                if (k2 > bestk) { bestk = k2; besti = i; }
            }
        }
        #pragma unroll
        for (int off = 16; off; off >>= 1) {
            unsigned long long ok = __shfl_xor_sync(FULLM, bestk, off);
            int oi = __shfl_xor_sync(FULLM, besti, off);
            if (ok > bestk) { bestk = ok; besti = oi; }
        }
        if (besti < 0) break;
        float4 pb = fbb4[b * CAP + besti];
        if (lane == 0) ((float4*)out)[b * PROP + p] = pb;
        float pa = (pb.z - pb.x) * (pb.w - pb.y);
        for (int i = lane; i < cnt; i += 32) {
            if (s_alive[i >> 5] & (1u << (i & 31))) {
                if (iou_ge07(pb, pa, fbb4[b * CAP + i]))
                    atomicAnd(&s_alive[i >> 5], ~(1u << (i & 31)));
            }
        }
        __syncwarp();
        ++p;
    }
}

// ---------------- launch ----------------
extern "C" void kernel_launch(void* const* d_in, const int* in_sizes, int n_in,
                              void* d_out, int out_size) {
    const float* probs   = (const float*)d_in[0];
    const float* bbox    = (const float*)d_in[1];
    const float* anchors = (const float*)d_in[2];
    float* out = (float*)d_out;
    (void)in_sizes; (void)n_in; (void)out_size;

    k_zero<<<512, 256>>>();

    dim3 gridN(256, BATCH);
    k_score_hist<<<gridN, 256>>>(probs);
    k_findbins<<<BATCH, 256>>>();
    dim3 gridC(64, BATCH);
    k_compact<<<gridC, 256>>>();
    dim3 gridH(8, BATCH);
    k_hist2c<<<gridH, 256>>>();
    k_findbin2<<<BATCH, 256>>>();
    dim3 gridT(8, BATCH);
    k_ctop<<<gridT, 256>>>();
    dim3 gridR(CAPW / 256, BATCH);
    k_rank<<<gridR, 256>>>();
    dim3 gridW(W / 256, BATCH);
    k_winbox<<<gridW, 256>>>(bbox, anchors);
    dim3 gridB(W / 64, W / 128, BATCH);
    k_build<<<gridB, 128>>>();
    k_nms_fast<<<BATCH, 32>>>(out);
    k_nms_exact<<<BATCH, 32>>>(out, bbox, anchors);
}

// round 10
// speedup vs baseline: 2.7398x; 1.6457x over previous
#include <cuda_runtime.h>
#include <cstdint>

#define BATCH 8
#define NVAL  261888
#define PRE   6000
#define CAP   8192
#define CAPW  3072
#define PROP  1000
#define W     2048         // NMS window (exact top-W sorted)
#define MWORDS 64          // matrix row words (W/32)
#define FULLM 0xFFFFFFFFu

// ---------------- scratch (static device globals; no allocation) ----------------
__device__ unsigned           g_u[BATCH * NVAL];
__device__ unsigned           g_hist1[BATCH * 65536];
__device__ unsigned           g_b1w[BATCH];
__device__ unsigned           g_abovew[BATCH];
__device__ unsigned           g_b1p[BATCH];
__device__ int                g_candcnt[BATCH];
__device__ int                g_topcnt[BATCH];
__device__ int                g_wvalid[BATCH];
__device__ unsigned long long g_cand[BATCH * CAP];
__device__ unsigned long long g_top[BATCH * CAPW];
__device__ float              g_winbox[BATCH * W * 4];
__device__ unsigned           g_walive[BATCH * 64];
__device__ unsigned           g_mat[(size_t)BATCH * W * MWORDS];   // 4 MB
__device__ float              g_fbb[BATCH * CAP * 4];
__device__ int                g_picks[BATCH * PROP];
__device__ int                g_fbcount[BATCH];
__device__ int                g_fbneed[BATCH];

__device__ __forceinline__ unsigned flip_f(float f) {
    unsigned b = __float_as_uint(f);
    unsigned mask = (unsigned)((int)b >> 31) | 0x80000000u;
    return b ^ mask;
}
__device__ __forceinline__ float unflip_f(unsigned u) {
    unsigned mask = (u >> 31) ? 0x80000000u : 0xFFFFFFFFu;
    return __uint_as_float(u ^ mask);
}

__device__ __forceinline__ float4 compute_box(const float* __restrict__ bbox,
                                              const float* __restrict__ anchors,
                                              int b, int idx) {
    int base = (b * NVAL + idx) * 4;
    float ay1 = anchors[base + 0];
    float ax1 = anchors[base + 1];
    float ay2 = anchors[base + 2];
    float ax2 = anchors[base + 3];
    float d0 = bbox[base + 0] * 0.1f;
    float d1 = bbox[base + 1] * 0.1f;
    float d2 = bbox[base + 2] * 0.2f;
    float d3 = bbox[base + 3] * 0.2f;
    float h = ay2 - ay1;
    float w = ax2 - ax1;
    float cy = ay1 + 0.5f * h;
    float cx = ax1 + 0.5f * w;
    cy = cy + d0 * h;
    cx = cx + d1 * w;
    h = h * expf(d2);
    w = w * expf(d3);
    float y1 = cy - 0.5f * h;
    float x1 = cx - 0.5f * w;
    float y2 = y1 + h;
    float x2 = x1 + w;
    return make_float4(fminf(fmaxf(y1, 0.f), 1.f),
                       fminf(fmaxf(x1, 0.f), 1.f),
                       fminf(fmaxf(y2, 0.f), 1.f),
                       fminf(fmaxf(x2, 0.f), 1.f));
}

__device__ __forceinline__ bool iou_ge07(float4 a, float fa, float4 c) {
    float yy1 = fmaxf(a.x, c.x);
    float xx1 = fmaxf(a.y, c.y);
    float yy2 = fminf(a.z, c.z);
    float xx2 = fminf(a.w, c.w);
    float inter = fmaxf(yy2 - yy1, 0.f) * fmaxf(xx2 - xx1, 0.f);
    float ca = (c.z - c.x) * (c.w - c.y);
    float u = ((fa + ca) - inter) + 1e-8f;
    return inter / u >= 0.7f;
}

__device__ __forceinline__ unsigned long long mk_key(unsigned u, unsigned n) {
    return ((unsigned long long)u << 18) | (unsigned long long)(0x3FFFFu - n);
}

// ---------------- K0: zero scratch ----------------
__global__ void k_zero() {
    int total = BATCH * 65536;
    for (int i = blockIdx.x * blockDim.x + threadIdx.x; i < total;
         i += gridDim.x * blockDim.x)
        g_hist1[i] = 0;
    int gid = blockIdx.x * blockDim.x + threadIdx.x;
    if (gid < BATCH) g_candcnt[gid] = 0;
    if (gid < BATCH * 64) g_walive[gid] = 0u;
}

// ---------------- K1: flip scores (float4), hist of high 16 bits ----------------
__global__ void k_score_hist(const float* __restrict__ probs) {
    int b = blockIdx.y;
    const float4* p4 = (const float4*)(probs + (size_t)b * NVAL * 2);
    uint2* u2 = (uint2*)(g_u + b * NVAL);
    const int n2 = NVAL / 2;   // float4 = 2 (neg,pos) pairs
    for (int i = blockIdx.x * blockDim.x + threadIdx.x; i < n2;
         i += gridDim.x * blockDim.x) {
        float4 v = p4[i];
        unsigned ua = flip_f(v.y);
        unsigned ub = flip_f(v.w);
        u2[i] = make_uint2(ua, ub);
        atomicAdd(&g_hist1[b * 65536 + (ua >> 16)], 1u);
        atomicAdd(&g_hist1[b * 65536 + (ub >> 16)], 1u);
    }
}

// ---------------- K2: coarse bins for rank W and rank PRE ----------------
__global__ void k_findbins() {
    __shared__ unsigned part[256];
    __shared__ unsigned chw[256], chp[256];
    __shared__ int s_cw, s_cp;
    __shared__ unsigned s_aw, s_ap;
    int b = blockIdx.x;
    const unsigned* hist = g_hist1 + b * 65536;
    unsigned s = 0;
    int base = threadIdx.x * 256;
    for (int i = 0; i < 256; ++i) s += hist[base + i];
    part[threadIdx.x] = s;
    __syncthreads();
    if (threadIdx.x == 0) {
        unsigned acc = 0;
        int cw = -1, cp = -1;
        unsigned aw = 0, ap = 0;
        for (int t = 255; t >= 0; --t) {
            unsigned pt = part[t];
            if (cw < 0 && acc + pt >= (unsigned)W)   { cw = t; aw = acc; }
            if (cp < 0 && acc + pt >= (unsigned)PRE) { cp = t; ap = acc; }
            acc += pt;
            if (cp >= 0) break;
        }
        if (cw < 0) cw = 0;
        if (cp < 0) cp = 0;
        s_cw = cw; s_cp = cp; s_aw = aw; s_ap = ap;
    }
    __syncthreads();
    chw[threadIdx.x] = hist[s_cw * 256 + threadIdx.x];
    chp[threadIdx.x] = hist[s_cp * 256 + threadIdx.x];
    __syncthreads();
    if (threadIdx.x == 0) {
        unsigned acc = s_aw;
        for (int i = 255; i >= 0; --i) {
            unsigned h = chw[i];
            if (acc + h >= (unsigned)W) {
                g_b1w[b] = (unsigned)(s_cw * 256 + i);
                g_abovew[b] = acc;
                break;
            }
            acc += h;
        }
        acc = s_ap;
        for (int i = 255; i >= 0; --i) {
            unsigned h = chp[i];
            if (acc + h >= (unsigned)PRE) {
                g_b1p[b] = (unsigned)(s_cp * 256 + i);
                break;
            }
            acc += h;
        }
    }
}

// ---------------- K3: vectorized compact (u >= coarse PRE threshold) ----------
__global__ void k_compact() {
    int b = blockIdx.y;
    unsigned T = g_b1p[b] << 16;
    int lane = threadIdx.x & 31;
    int gid = blockIdx.x * blockDim.x + threadIdx.x;
    int stride = gridDim.x * blockDim.x;
    const uint4* u4 = (const uint4*)(g_u + b * NVAL);
    const int n4 = NVAL / 4;
    int iters = (n4 + stride - 1) / stride;
    for (int it = 0; it < iters; ++it) {
        int i = gid + it * stride;
        uint4 v = make_uint4(0, 0, 0, 0);
        int c = 0;
        bool inb = (i < n4);
        if (inb) {
            v = u4[i];
            c = (v.x >= T) + (v.y >= T) + (v.z >= T) + (v.w >= T);
        }
        int incl = c;
        #pragma unroll
        for (int off = 1; off < 32; off <<= 1) {
            int t = __shfl_up_sync(FULLM, incl, off);
            if (lane >= off) incl += t;
        }
        int total = __shfl_sync(FULLM, incl, 31);
        if (total == 0) continue;
        int basepos = 0;
        if (lane == 31) basepos = atomicAdd(&g_candcnt[b], total);
        basepos = __shfl_sync(FULLM, basepos, 31);
        if (inb && c) {
            int pos = basepos + incl - c;
            unsigned n0 = (unsigned)(i * 4);
            if (v.x >= T) { if (pos < CAP) g_cand[b * CAP + pos] = mk_key(v.x, n0 + 0); ++pos; }
            if (v.y >= T) { if (pos < CAP) g_cand[b * CAP + pos] = mk_key(v.y, n0 + 1); ++pos; }
            if (v.z >= T) { if (pos < CAP) g_cand[b * CAP + pos] = mk_key(v.z, n0 + 2); ++pos; }
            if (v.w >= T) { if (pos < CAP) g_cand[b * CAP + pos] = mk_key(v.w, n0 + 3); ++pos; }
        }
    }
}

// ---------------- K4: fused exact rank-W threshold + top-set compact ----------
__global__ void k_select() {
    __shared__ unsigned bins[256];
    __shared__ int s_d1;
    __shared__ unsigned s_K2;
    __shared__ unsigned s_T;
    __shared__ int s_cnt2;
    int b = blockIdx.x;
    int tid = threadIdx.x;
    int cnt = g_candcnt[b];
    if (cnt > CAP) cnt = CAP;
    unsigned b1 = g_b1w[b];
    unsigned K = (unsigned)W - g_abovew[b];   // 1..W

    // pass 1: bins over bits[8:16) for members of coarse bin b1
    bins[tid] = 0;
    __syncthreads();
    for (int i = tid; i < cnt; i += 256) {
        unsigned u = (unsigned)(g_cand[b * CAP + i] >> 18);
        if ((u >> 16) == b1) atomicAdd(&bins[(u >> 8) & 0xFF], 1u);
    }
    __syncthreads();
    if (tid == 0) {
        unsigned acc = 0;
        int d1 = 0;
        for (int d = 255; d >= 0; --d) {
            unsigned h = bins[d];
            if (acc + h >= K) { d1 = d; break; }
            acc += h;
        }
        s_d1 = d1; s_K2 = K - acc;
    }
    __syncthreads();
    unsigned pre = (b1 << 8) | (unsigned)s_d1;
    unsigned K2 = s_K2;

    // pass 2: bins over bits[0:8) for members with matching top-24 bits
    bins[tid] = 0;
    __syncthreads();
    for (int i = tid; i < cnt; i += 256) {
        unsigned u = (unsigned)(g_cand[b * CAP + i] >> 18);
        if ((u >> 8) == pre) atomicAdd(&bins[u & 0xFF], 1u);
    }
    __syncthreads();
    if (tid == 0) {
        unsigned acc = 0;
        int d0 = 0;
        for (int d = 255; d >= 0; --d) {
            unsigned h = bins[d];
            if (acc + h >= K2) { d0 = d; break; }
            acc += h;
        }
        s_T = (pre << 8) | (unsigned)d0;
        s_cnt2 = 0;
    }
    __syncthreads();
    unsigned long long Tk = ((unsigned long long)s_T) << 18;

    // pass 3: compact top set
    for (int i = tid; i < cnt; i += 256) {
        unsigned long long key = g_cand[b * CAP + i];
        if (key >= Tk) {
            int pos = atomicAdd(&s_cnt2, 1);
            if (pos < CAPW) g_top[b * CAPW + pos] = key;
        }
    }
    __syncthreads();
    if (tid == 0) {
        int tc = s_cnt2;
        g_topcnt[b] = tc;
        g_wvalid[b] = (tc >= W && tc <= CAPW) ? 1 : 0;
    }
}

// ---------------- K5: counting-rank + box + alive (fused) ----------------
__global__ void k_rank(const float* __restrict__ bbox,
                       const float* __restrict__ anchors) {
    __shared__ unsigned long long tile[256];
    int b = blockIdx.y;
    if (!g_wvalid[b]) return;
    int tc = g_topcnt[b];
    int i = blockIdx.x * blockDim.x + threadIdx.x;
    unsigned long long key = (i < tc) ? g_top[b * CAPW + i] : 0ULL;
    int rank = 0;
    for (int t0 = 0; t0 < tc; t0 += 256) {
        int j = t0 + threadIdx.x;
        tile[threadIdx.x] = (j < tc) ? g_top[b * CAPW + j] : 0ULL;
        __syncthreads();
        int lim = tc - t0; if (lim > 256) lim = 256;
        #pragma unroll 4
        for (int j2 = 0; j2 < lim; ++j2)
            rank += (tile[j2] > key);
        __syncthreads();
    }
    if (i < tc && rank < W) {
        unsigned idx = 0x3FFFFu - (unsigned)(key & 0x3FFFFu);
        float4 box = (idx < (unsigned)NVAL)
            ? compute_box(bbox, anchors, b, (int)idx)
            : make_float4(0.f, 0.f, 0.f, 0.f);
        ((float4*)g_winbox)[b * W + rank] = box;
        if (unflip_f((unsigned)(key >> 18)) >= 0.5f)
            atomicOr(&g_walive[b * 64 + (rank >> 5)], 1u << (rank & 31));
    }
}

// ---------------- K6: windowed suppression matrix build ----------------
__global__ void k_build() {
    int bx = blockIdx.x, by = blockIdx.y, b = blockIdx.z;
    if (bx * 64 + 64 <= by * 128) return;
    __shared__ float4 cb[64];
    __shared__ float  ca[64];
    int t = threadIdx.x;
    int j0 = bx * 64;
    const float4* boxes4 = (const float4*)g_winbox;
    if (t < 64) {
        float4 a = boxes4[b * W + j0 + t];
        cb[t] = a;
        ca[t] = (a.z - a.x) * (a.w - a.y);
    }
    __syncthreads();
    int i = by * 128 + t;
    float4 r = boxes4[b * W + i];
    float ra = (r.z - r.x) * (r.w - r.y);
    unsigned w0 = 0, w1 = 0;
    #pragma unroll 8
    for (int jj = 0; jj < 64; ++jj) {
        int j = j0 + jj;
        bool sup = false;
        if (j > i) {
            float4 c = cb[jj];
            float yy1 = fmaxf(r.x, c.x);
            float xx1 = fmaxf(r.y, c.y);
            float yy2 = fminf(r.z, c.z);
            float xx2 = fminf(r.w, c.w);
            float inter = fmaxf(yy2 - yy1, 0.f) * fmaxf(xx2 - xx1, 0.f);
            float u = ((ra + ca[jj]) - inter) + 1e-8f;
            if (inter >= 0.700007f * u)       sup = true;
            else if (inter <= 0.699993f * u)  sup = false;
            else                              sup = (inter / u >= 0.7f);
        }
        if (jj < 32) w0 |= ((unsigned)sup) << jj;
        else         w1 |= ((unsigned)sup) << (jj - 32);
    }
    uint2* rb = (uint2*)(g_mat + ((size_t)b * W + i) * MWORDS + bx * 2);
    *rb = make_uint2(w0, w1);
}

// ---------------- K7: full-word frontier NMS (one warp per batch) -------------
__global__ void k_nms_fast(float* __restrict__ out) {
    __shared__ int s_picks[PROP];
    int b = blockIdx.x;
    int lane = threadIdx.x;
    const float4* wbox4 = (const float4*)g_winbox;

    for (int t = lane; t < PROP * 4; t += 32) out[b * PROP * 4 + t] = 0.f;

    int p = 0;
    if (g_wvalid[b]) {
        unsigned a0 = g_walive[b * 64 + lane];
        unsigned a1 = g_walive[b * 64 + 32 + lane];
        const unsigned* mat = g_mat + (size_t)b * W * MWORDS;

        while (p < PROP) {
            unsigned bal0 = __ballot_sync(FULLM, a0 != 0u);
            unsigned bal1 = __ballot_sync(FULLM, a1 != 0u);
            if (!bal0 && !bal1) break;
            int F = bal0 ? (__ffs(bal0) - 1) : (32 + __ffs(bal1) - 1);
            unsigned w0 = __shfl_sync(FULLM, (F < 32) ? a0 : a1, F & 31);

            const unsigned* rowbase = mat + (size_t)(F * 32) * MWORDS;

            // frontier words of all 32 rows of this word-block (compile-time regs)
            unsigned fw[32];
            #pragma unroll
            for (int q = 0; q < 32; ++q) {
                unsigned v0 = rowbase[q * MWORDS + lane];
                unsigned v1 = rowbase[q * MWORDS + 32 + lane];
                fw[q] = __shfl_sync(FULLM, (F < 32) ? v0 : v1, F & 31);
            }

            // serial greedy chain over word F (pure ALU, uniform across lanes)
            unsigned t = w0, acc = 0;
            #pragma unroll
            for (int q = 0; q < 32; ++q) {
                if ((t & (1u << q)) && p < PROP) {
                    acc |= 1u << q;
                    if (lane == 0) s_picks[p] = F * 32 + q;
                    ++p;
                    t &= ~fw[q];
                }
            }

            // apply accepted rows to distributed alive (L1-hot reloads)
            unsigned or0 = 0, or1 = 0;
            #pragma unroll
            for (int q = 0; q < 32; ++q) {
                if (acc & (1u << q)) {
                    or0 |= rowbase[q * MWORDS + lane];
                    or1 |= rowbase[q * MWORDS + 32 + lane];
                }
            }
            a0 &= ~or0;
            a1 &= ~or1;
            // word F fully resolved
            if (F < 32) { if (lane == F) a0 = 0; }
            else        { if (lane == F - 32) a1 = 0; }
        }
    }

    __syncwarp();
    float4* out4 = (float4*)out;
    for (int q = lane; q < p; q += 32) {
        int pos = s_picks[q];
        out4[b * PROP + q] = wbox4[b * W + pos];
        g_picks[b * PROP + q] = pos;
    }
    if (lane == 0) {
        g_fbcount[b] = p;
        g_fbneed[b] = (p < PROP) ? 1 : 0;
    }
}

// ---------------- K8: exact fallback kernel (early-exits when unneeded) ------
__global__ void k_nms_exact(float* __restrict__ out,
                            const float* __restrict__ bbox,
                            const float* __restrict__ anchors) {
    __shared__ unsigned s_alive[CAP / 32];
    int b = blockIdx.x;
    if (!g_fbneed[b]) return;
    int lane = threadIdx.x;
    const float4* wbox4 = (const float4*)g_winbox;
    int p_fast = g_fbcount[b];
    int p = p_fast;

    int cnt = g_candcnt[b];
    if (cnt > CAP) cnt = CAP;
    float4* fbb4 = (float4*)g_fbb;

    for (int i = lane; i < cnt; i += 32) {
        unsigned long long key = g_cand[b * CAP + i];
        unsigned idx = 0x3FFFFu - (unsigned)(key & 0x3FFFFu);
        fbb4[b * CAP + i] = (idx < (unsigned)NVAL)
            ? compute_box(bbox, anchors, b, (int)idx)
            : make_float4(0.f, 0.f, 0.f, 0.f);
    }
    for (int wd = lane; wd < CAP / 32; wd += 32) s_alive[wd] = 0u;
    __syncwarp();
    for (int i = lane; i < cnt; i += 32) {
        unsigned long long key = g_cand[b * CAP + i];
        int rank = 0;
        for (int j = 0; j < cnt; ++j)
            rank += (g_cand[b * CAP + j] > key);
        bool live = (rank < PRE) &&
                    (unflip_f((unsigned)(key >> 18)) >= 0.5f);
        if (live) atomicOr(&s_alive[i >> 5], 1u << (i & 31));
    }
    __syncwarp();
    for (int q = 0; q < p_fast; ++q) {
        float4 pb = wbox4[b * W + g_picks[b * PROP + q]];
        float pa = (pb.z - pb.x) * (pb.w - pb.y);
        for (int i = lane; i < cnt; i += 32) {
            if (s_alive[i >> 5] & (1u << (i & 31))) {
                if (iou_ge07(pb, pa, fbb4[b * CAP + i]))
                    atomicAnd(&s_alive[i >> 5], ~(1u << (i & 31)));
            }
        }
        __syncwarp();
    }
    while (p < PROP) {
        unsigned long long bestk = 0ULL;
        int besti = -1;
        for (int i = lane; i < cnt; i += 32) {
            if (s_alive[i >> 5] & (1u << (i & 31))) {
                unsigned long long k2 = g_cand[b * CAP + i];
                if (k2 > bestk) { bestk = k2; besti = i; }
            }
        }
        #pragma unroll
        for (int off = 16; off; off >>= 1) {
            unsigned long long ok = __shfl_xor_sync(FULLM, bestk, off);
            int oi = __shfl_xor_sync(FULLM, besti, off);
            if (ok > bestk) { bestk = ok; besti = oi; }
        }
        if (besti < 0) break;
        float4 pb = fbb4[b * CAP + besti];
        if (lane == 0) ((float4*)out)[b * PROP + p] = pb;
        float pa = (pb.z - pb.x) * (pb.w - pb.y);
        for (int i = lane; i < cnt; i += 32) {
            if (s_alive[i >> 5] & (1u << (i & 31))) {
                if (iou_ge07(pb, pa, fbb4[b * CAP + i]))
                    atomicAnd(&s_alive[i >> 5], ~(1u << (i & 31)));
            }
        }
        __syncwarp();
        ++p;
    }
}

// ---------------- launch ----------------
extern "C" void kernel_launch(void* const* d_in, const int* in_sizes, int n_in,
                              void* d_out, int out_size) {
    const float* probs   = (const float*)d_in[0];
    const float* bbox    = (const float*)d_in[1];
    const float* anchors = (const float*)d_in[2];
    float* out = (float*)d_out;
    (void)in_sizes; (void)n_in; (void)out_size;

    k_zero<<<512, 256>>>();

    dim3 gridN(128, BATCH);
    k_score_hist<<<gridN, 256>>>(probs);
    k_findbins<<<BATCH, 256>>>();
    dim3 gridC(64, BATCH);
    k_compact<<<gridC, 256>>>();
    k_select<<<BATCH, 256>>>();
    dim3 gridR(CAPW / 256, BATCH);
    k_rank<<<gridR, 256>>>(bbox, anchors);
    dim3 gridB(W / 64, W / 128, BATCH);
    k_build<<<gridB, 128>>>();
    k_nms_fast<<<BATCH, 32>>>(out);
    k_nms_exact<<<BATCH, 32>>>(out, bbox, anchors);
}

// round 11
// speedup vs baseline: 2.9000x; 1.0585x over previous
#include <cuda_runtime.h>
#include <cstdint>

#define BATCH 8
#define NVAL  261888
#define PRE   6000
#define CAP   8192
#define CAPW  3072
#define PROP  1000
#define W     2048         // NMS window (exact top-W sorted)
#define MWORDS 64          // matrix row words (W/32)
#define FULLM 0xFFFFFFFFu

// ---------------- scratch (static device globals; no allocation) ----------------
__device__ unsigned           g_u[BATCH * NVAL];
__device__ unsigned           g_hist1[BATCH * 65536];
__device__ unsigned           g_b1w[BATCH];
__device__ unsigned           g_abovew[BATCH];
__device__ unsigned           g_b1p[BATCH];
__device__ int                g_candcnt[BATCH];
__device__ int                g_topcnt[BATCH];
__device__ int                g_wvalid[BATCH];
__device__ unsigned long long g_cand[BATCH * CAP];
__device__ unsigned long long g_top[BATCH * CAPW];
__device__ float              g_winbox[BATCH * W * 4];
__device__ unsigned           g_walive[BATCH * 64];
__device__ unsigned           g_mat[(size_t)BATCH * W * MWORDS];   // 4 MB
__device__ float              g_fbb[BATCH * CAP * 4];
__device__ int                g_picks[BATCH * PROP];
__device__ int                g_fbcount[BATCH];
__device__ int                g_fbneed[BATCH];

__device__ __forceinline__ unsigned flip_f(float f) {
    unsigned b = __float_as_uint(f);
    unsigned mask = (unsigned)((int)b >> 31) | 0x80000000u;
    return b ^ mask;
}
__device__ __forceinline__ float unflip_f(unsigned u) {
    unsigned mask = (u >> 31) ? 0x80000000u : 0xFFFFFFFFu;
    return __uint_as_float(u ^ mask);
}

__device__ __forceinline__ float4 compute_box(const float* __restrict__ bbox,
                                              const float* __restrict__ anchors,
                                              int b, int idx) {
    int base = (b * NVAL + idx) * 4;
    float ay1 = anchors[base + 0];
    float ax1 = anchors[base + 1];
    float ay2 = anchors[base + 2];
    float ax2 = anchors[base + 3];
    float d0 = bbox[base + 0] * 0.1f;
    float d1 = bbox[base + 1] * 0.1f;
    float d2 = bbox[base + 2] * 0.2f;
    float d3 = bbox[base + 3] * 0.2f;
    float h = ay2 - ay1;
    float w = ax2 - ax1;
    float cy = ay1 + 0.5f * h;
    float cx = ax1 + 0.5f * w;
    cy = cy + d0 * h;
    cx = cx + d1 * w;
    h = h * expf(d2);
    w = w * expf(d3);
    float y1 = cy - 0.5f * h;
    float x1 = cx - 0.5f * w;
    float y2 = y1 + h;
    float x2 = x1 + w;
    return make_float4(fminf(fmaxf(y1, 0.f), 1.f),
                       fminf(fmaxf(x1, 0.f), 1.f),
                       fminf(fmaxf(y2, 0.f), 1.f),
                       fminf(fmaxf(x2, 0.f), 1.f));
}

__device__ __forceinline__ bool iou_ge07(float4 a, float fa, float4 c) {
    float yy1 = fmaxf(a.x, c.x);
    float xx1 = fmaxf(a.y, c.y);
    float yy2 = fminf(a.z, c.z);
    float xx2 = fminf(a.w, c.w);
    float inter = fmaxf(yy2 - yy1, 0.f) * fmaxf(xx2 - xx1, 0.f);
    float ca = (c.z - c.x) * (c.w - c.y);
    float u = ((fa + ca) - inter) + 1e-8f;
    return inter / u >= 0.7f;
}

__device__ __forceinline__ unsigned long long mk_key(unsigned u, unsigned n) {
    return ((unsigned long long)u << 18) | (unsigned long long)(0x3FFFFu - n);
}

// ---------------- K1: flip scores (float4), hist of high 16 bits ----------------
// hist1 arrives zeroed (module init on first run; k_compact re-zeroes each run).
__global__ void k_score_hist(const float* __restrict__ probs) {
    int b = blockIdx.y;
    const float4* p4 = (const float4*)(probs + (size_t)b * NVAL * 2);
    uint2* u2 = (uint2*)(g_u + b * NVAL);
    const int n2 = NVAL / 2;
    for (int i = blockIdx.x * blockDim.x + threadIdx.x; i < n2;
         i += gridDim.x * blockDim.x) {
        float4 v = p4[i];
        unsigned ua = flip_f(v.y);
        unsigned ub = flip_f(v.w);
        u2[i] = make_uint2(ua, ub);
        atomicAdd(&g_hist1[b * 65536 + (ua >> 16)], 1u);
        atomicAdd(&g_hist1[b * 65536 + (ub >> 16)], 1u);
    }
}

// ---------------- K2: coarse bins for rank W and rank PRE ----------------
__global__ void k_findbins() {
    __shared__ unsigned part[256];
    __shared__ unsigned chw[256], chp[256];
    __shared__ int s_cw, s_cp;
    __shared__ unsigned s_aw, s_ap;
    int b = blockIdx.x;
    const unsigned* hist = g_hist1 + b * 65536;
    unsigned s = 0;
    int base = threadIdx.x * 256;
    for (int i = 0; i < 256; ++i) s += hist[base + i];
    part[threadIdx.x] = s;
    __syncthreads();
    if (threadIdx.x == 0) {
        unsigned acc = 0;
        int cw = -1, cp = -1;
        unsigned aw = 0, ap = 0;
        for (int t = 255; t >= 0; --t) {
            unsigned pt = part[t];
            if (cw < 0 && acc + pt >= (unsigned)W)   { cw = t; aw = acc; }
            if (cp < 0 && acc + pt >= (unsigned)PRE) { cp = t; ap = acc; }
            acc += pt;
            if (cp >= 0) break;
        }
        if (cw < 0) cw = 0;
        if (cp < 0) cp = 0;
        s_cw = cw; s_cp = cp; s_aw = aw; s_ap = ap;
    }
    __syncthreads();
    chw[threadIdx.x] = hist[s_cw * 256 + threadIdx.x];
    chp[threadIdx.x] = hist[s_cp * 256 + threadIdx.x];
    __syncthreads();
    if (threadIdx.x == 0) {
        unsigned acc = s_aw;
        for (int i = 255; i >= 0; --i) {
            unsigned h = chw[i];
            if (acc + h >= (unsigned)W) {
                g_b1w[b] = (unsigned)(s_cw * 256 + i);
                g_abovew[b] = acc;
                break;
            }
            acc += h;
        }
        acc = s_ap;
        for (int i = 255; i >= 0; --i) {
            unsigned h = chp[i];
            if (acc + h >= (unsigned)PRE) {
                g_b1p[b] = (unsigned)(s_cp * 256 + i);
                break;
            }
            acc += h;
        }
    }
}

// ---------------- K3: block-aggregated compact + hist1 re-zero ----------------
// grid (64, BATCH), 256 threads; each block covers 1024 uint4 = 4096 values.
__global__ void k_compact() {
    __shared__ int s_warpoff[8];
    __shared__ int s_base;
    int b = blockIdx.y;
    unsigned T = g_b1p[b] << 16;
    int tid = threadIdx.x, lane = tid & 31, wid = tid >> 5;
    const uint4* u4 = (const uint4*)(g_u + b * NVAL);
    const int n4 = NVAL / 4;
    int base_i = blockIdx.x * 1024;

    uint4 v[4];
    int c = 0;
    #pragma unroll
    for (int k = 0; k < 4; ++k) {
        int i = base_i + k * 256 + tid;
        v[k] = (i < n4) ? u4[i] : make_uint4(0, 0, 0, 0);
        c += (v[k].x >= T) + (v[k].y >= T) + (v[k].z >= T) + (v[k].w >= T);
    }
    int incl = c;
    #pragma unroll
    for (int off = 1; off < 32; off <<= 1) {
        int t = __shfl_up_sync(FULLM, incl, off);
        if (lane >= off) incl += t;
    }
    if (lane == 31) s_warpoff[wid] = incl;
    __syncthreads();
    if (tid == 0) {
        int tot = 0;
        #pragma unroll
        for (int w = 0; w < 8; ++w) {
            int t = s_warpoff[w];
            s_warpoff[w] = tot;
            tot += t;
        }
        s_base = tot ? atomicAdd(&g_candcnt[b], tot) : 0;
    }
    __syncthreads();
    int pos = s_base + s_warpoff[wid] + incl - c;
    #pragma unroll
    for (int k = 0; k < 4; ++k) {
        int i = base_i + k * 256 + tid;
        unsigned n0 = (unsigned)(i * 4);
        if (v[k].x >= T) { if (pos < CAP) g_cand[b * CAP + pos] = mk_key(v[k].x, n0 + 0); ++pos; }
        if (v[k].y >= T) { if (pos < CAP) g_cand[b * CAP + pos] = mk_key(v[k].y, n0 + 1); ++pos; }
        if (v[k].z >= T) { if (pos < CAP) g_cand[b * CAP + pos] = mk_key(v[k].z, n0 + 2); ++pos; }
        if (v[k].w >= T) { if (pos < CAP) g_cand[b * CAP + pos] = mk_key(v[k].w, n0 + 3); ++pos; }
    }
    // re-zero this block's hist1 slice (consumed by k_findbins already)
    ((uint4*)(g_hist1 + b * 65536 + blockIdx.x * 1024))[tid] = make_uint4(0, 0, 0, 0);
}

// ---------------- K4: fused exact rank-W threshold + top-set compact ----------
__global__ void k_select() {
    __shared__ unsigned su[CAP];      // 32 KB score-word cache
    __shared__ unsigned bins[256];
    __shared__ int s_d1;
    __shared__ unsigned s_K2;
    __shared__ unsigned s_T;
    __shared__ int s_cnt2;
    int b = blockIdx.x;
    int tid = threadIdx.x;
    int cnt = g_candcnt[b];
    if (cnt > CAP) cnt = CAP;
    unsigned b1 = g_b1w[b];
    unsigned K = (unsigned)W - g_abovew[b];   // 1..W

    for (int i = tid; i < cnt; i += 256)
        su[i] = (unsigned)(g_cand[b * CAP + i] >> 18);
    bins[tid] = 0;
    __syncthreads();
    for (int i = tid; i < cnt; i += 256) {
        unsigned u = su[i];
        if ((u >> 16) == b1) atomicAdd(&bins[(u >> 8) & 0xFF], 1u);
    }
    __syncthreads();
    if (tid == 0) {
        unsigned acc = 0;
        int d1 = 0;
        for (int d = 255; d >= 0; --d) {
            unsigned h = bins[d];
            if (acc + h >= K) { d1 = d; break; }
            acc += h;
        }
        s_d1 = d1; s_K2 = K - acc;
    }
    __syncthreads();
    unsigned pre = (b1 << 8) | (unsigned)s_d1;
    unsigned K2 = s_K2;
    bins[tid] = 0;
    __syncthreads();
    for (int i = tid; i < cnt; i += 256) {
        unsigned u = su[i];
        if ((u >> 8) == pre) atomicAdd(&bins[u & 0xFF], 1u);
    }
    __syncthreads();
    if (tid == 0) {
        unsigned acc = 0;
        int d0 = 0;
        for (int d = 255; d >= 0; --d) {
            unsigned h = bins[d];
            if (acc + h >= K2) { d0 = d; break; }
            acc += h;
        }
        s_T = (pre << 8) | (unsigned)d0;
        s_cnt2 = 0;
    }
    __syncthreads();
    unsigned T = s_T;
    for (int i = tid; i < cnt; i += 256) {
        if (su[i] >= T) {   // key >= (T<<18) iff u >= T
            int pos = atomicAdd(&s_cnt2, 1);
            if (pos < CAPW) g_top[b * CAPW + pos] = g_cand[b * CAP + i];
        }
    }
    __syncthreads();
    if (tid == 0) {
        int tc = s_cnt2;
        g_topcnt[b] = tc;
        g_wvalid[b] = (tc >= W && tc <= CAPW) ? 1 : 0;
    }
}

// ---------------- K5: counting-rank + box + alive (fused) ----------------
__global__ void k_rank(const float* __restrict__ bbox,
                       const float* __restrict__ anchors) {
    __shared__ unsigned long long tile[256];
    int b = blockIdx.y;
    if (!g_wvalid[b]) return;
    int tc = g_topcnt[b];
    int i = blockIdx.x * blockDim.x + threadIdx.x;
    unsigned long long key = (i < tc) ? g_top[b * CAPW + i] : 0ULL;
    int rank = 0;
    for (int t0 = 0; t0 < tc; t0 += 256) {
        int j = t0 + threadIdx.x;
        tile[threadIdx.x] = (j < tc) ? g_top[b * CAPW + j] : 0ULL;
        __syncthreads();
        int lim = tc - t0; if (lim > 256) lim = 256;
        #pragma unroll 4
        for (int j2 = 0; j2 < lim; ++j2)
            rank += (tile[j2] > key);
        __syncthreads();
    }
    if (i < tc && rank < W) {
        unsigned idx = 0x3FFFFu - (unsigned)(key & 0x3FFFFu);
        float4 box = (idx < (unsigned)NVAL)
            ? compute_box(bbox, anchors, b, (int)idx)
            : make_float4(0.f, 0.f, 0.f, 0.f);
        ((float4*)g_winbox)[b * W + rank] = box;
        if (unflip_f((unsigned)(key >> 18)) >= 0.5f)
            atomicOr(&g_walive[b * 64 + (rank >> 5)], 1u << (rank & 31));
    }
}

// ---------------- K6: windowed suppression matrix build ----------------
__global__ void k_build() {
    int bx = blockIdx.x, by = blockIdx.y, b = blockIdx.z;
    if (bx * 64 + 64 <= by * 128) return;
    __shared__ float4 cb[64];
    __shared__ float  ca[64];
    int t = threadIdx.x;
    int j0 = bx * 64;
    const float4* boxes4 = (const float4*)g_winbox;
    if (t < 64) {
        float4 a = boxes4[b * W + j0 + t];
        cb[t] = a;
        ca[t] = (a.z - a.x) * (a.w - a.y);
    }
    __syncthreads();
    int i = by * 128 + t;
    float4 r = boxes4[b * W + i];
    float ra = (r.z - r.x) * (r.w - r.y);
    unsigned w0 = 0, w1 = 0;
    #pragma unroll 8
    for (int jj = 0; jj < 64; ++jj) {
        int j = j0 + jj;
        bool sup = false;
        if (j > i) {
            float4 c = cb[jj];
            float yy1 = fmaxf(r.x, c.x);
            float xx1 = fmaxf(r.y, c.y);
            float yy2 = fminf(r.z, c.z);
            float xx2 = fminf(r.w, c.w);
            float inter = fmaxf(yy2 - yy1, 0.f) * fmaxf(xx2 - xx1, 0.f);
            float u = ((ra + ca[jj]) - inter) + 1e-8f;
            if (inter >= 0.700007f * u)       sup = true;
            else if (inter <= 0.699993f * u)  sup = false;
            else                              sup = (inter / u >= 0.7f);
        }
        if (jj < 32) w0 |= ((unsigned)sup) << jj;
        else         w1 |= ((unsigned)sup) << (jj - 32);
    }
    uint2* rb = (uint2*)(g_mat + ((size_t)b * W + i) * MWORDS + bx * 2);
    *rb = make_uint2(w0, w1);
}

// ---------------- K7: full-word frontier NMS (one warp per batch) -------------
__global__ void __launch_bounds__(32, 1) k_nms_fast(float* __restrict__ out) {
    __shared__ int s_picks[PROP];
    int b = blockIdx.x;
    int lane = threadIdx.x;
    const float4* wbox4 = (const float4*)g_winbox;

    for (int t = lane; t < PROP * 4; t += 32) out[b * PROP * 4 + t] = 0.f;

    int valid = g_wvalid[b];
    unsigned a0 = g_walive[b * 64 + lane];
    unsigned a1 = g_walive[b * 64 + 32 + lane];
    // re-zero for next replay (rank atomicOr needs zeros)
    g_walive[b * 64 + lane] = 0u;
    g_walive[b * 64 + 32 + lane] = 0u;

    int p = 0;
    if (valid) {
        const unsigned* mat = g_mat + (size_t)b * W * MWORDS;
        while (p < PROP) {
            unsigned bal0 = __ballot_sync(FULLM, a0 != 0u);
            unsigned bal1 = __ballot_sync(FULLM, a1 != 0u);
            if (!bal0 && !bal1) break;
            int F = bal0 ? (__ffs(bal0) - 1) : (32 + __ffs(bal1) - 1);
            unsigned w0 = __shfl_sync(FULLM, (F < 32) ? a0 : a1, F & 31);

            const unsigned* rowbase = mat + (size_t)(F * 32) * MWORDS;

            // load all 32 rows of this word-block into registers
            unsigned v0[32], v1[32], fw[32];
            #pragma unroll
            for (int q = 0; q < 32; ++q) {
                v0[q] = rowbase[q * MWORDS + lane];
                v1[q] = rowbase[q * MWORDS + 32 + lane];
            }
            #pragma unroll
            for (int q = 0; q < 32; ++q)
                fw[q] = __shfl_sync(FULLM, (F < 32) ? v0[q] : v1[q], F & 31);

            // serial greedy chain over word F (pure ALU, uniform across lanes)
            unsigned t = w0, acc = 0;
            #pragma unroll
            for (int q = 0; q < 32; ++q) {
                if ((t & (1u << q)) && p < PROP) {
                    acc |= 1u << q;
                    if (lane == 0) s_picks[p] = F * 32 + q;
                    ++p;
                    t &= ~fw[q];
                }
            }

            // apply accepted rows (from registers)
            unsigned or0 = 0, or1 = 0;
            #pragma unroll
            for (int q = 0; q < 32; ++q) {
                if (acc & (1u << q)) { or0 |= v0[q]; or1 |= v1[q]; }
            }
            a0 &= ~or0;
            a1 &= ~or1;
            if (F < 32) { if (lane == F) a0 = 0; }
            else        { if (lane == F - 32) a1 = 0; }
        }
    }

    __syncwarp();
    float4* out4 = (float4*)out;
    for (int q = lane; q < p; q += 32) {
        int pos = s_picks[q];
        out4[b * PROP + q] = wbox4[b * W + pos];
        g_picks[b * PROP + q] = pos;
    }
    if (lane == 0) {
        g_fbcount[b] = p;
        g_fbneed[b] = (p < PROP) ? 1 : 0;
    }
}

// ---------------- K8: exact fallback kernel (early-exits when unneeded) ------
__global__ void k_nms_exact(float* __restrict__ out,
                            const float* __restrict__ bbox,
                            const float* __restrict__ anchors) {
    __shared__ unsigned s_alive[CAP / 32];
    int b = blockIdx.x;
    int lane = threadIdx.x;
    int cnt = g_candcnt[b];
    if (cnt > CAP) cnt = CAP;
    if (lane == 0) g_candcnt[b] = 0;   // restore for next replay
    if (!g_fbneed[b]) return;

    const float4* wbox4 = (const float4*)g_winbox;
    int p_fast = g_fbcount[b];
    int p = p_fast;
    float4* fbb4 = (float4*)g_fbb;

    for (int i = lane; i < cnt; i += 32) {
        unsigned long long key = g_cand[b * CAP + i];
        unsigned idx = 0x3FFFFu - (unsigned)(key & 0x3FFFFu);
        fbb4[b * CAP + i] = (idx < (unsigned)NVAL)
            ? compute_box(bbox, anchors, b, (int)idx)
            : make_float4(0.f, 0.f, 0.f, 0.f);
    }
    for (int wd = lane; wd < CAP / 32; wd += 32) s_alive[wd] = 0u;
    __syncwarp();
    for (int i = lane; i < cnt; i += 32) {
        unsigned long long key = g_cand[b * CAP + i];
        int rank = 0;
        for (int j = 0; j < cnt; ++j)
            rank += (g_cand[b * CAP + j] > key);
        bool live = (rank < PRE) &&
                    (unflip_f((unsigned)(key >> 18)) >= 0.5f);
        if (live) atomicOr(&s_alive[i >> 5], 1u << (i & 31));
    }
    __syncwarp();
    for (int q = 0; q < p_fast; ++q) {
        float4 pb = wbox4[b * W + g_picks[b * PROP + q]];
        float pa = (pb.z - pb.x) * (pb.w - pb.y);
        for (int i = lane; i < cnt; i += 32) {
            if (s_alive[i >> 5] & (1u << (i & 31))) {
                if (iou_ge07(pb, pa, fbb4[b * CAP + i]))
                    atomicAnd(&s_alive[i >> 5], ~(1u << (i & 31)));
            }
        }
        __syncwarp();
    }
    while (p < PROP) {
        unsigned long long bestk = 0ULL;
        int besti = -1;
        for (int i = lane; i < cnt; i += 32) {
            if (s_alive[i >> 5] & (1u << (i & 31))) {
                unsigned long long k2 = g_cand[b * CAP + i];
                if (k2 > bestk) { bestk = k2; besti = i; }
            }
        }
        #pragma unroll
        for (int off = 16; off; off >>= 1) {
            unsigned long long ok = __shfl_xor_sync(FULLM, bestk, off);
            int oi = __shfl_xor_sync(FULLM, besti, off);
            if (ok > bestk) { bestk = ok; besti = oi; }
        }
        if (besti < 0) break;
        float4 pb = fbb4[b * CAP + besti];
        if (lane == 0) ((float4*)out)[b * PROP + p] = pb;
        float pa = (pb.z - pb.x) * (pb.w - pb.y);
        for (int i = lane; i < cnt; i += 32) {
            if (s_alive[i >> 5] & (1u << (i & 31))) {
                if (iou_ge07(pb, pa, fbb4[b * CAP + i]))
                    atomicAnd(&s_alive[i >> 5], ~(1u << (i & 31)));
            }
        }
        __syncwarp();
        ++p;
    }
}

// ---------------- launch ----------------
extern "C" void kernel_launch(void* const* d_in, const int* in_sizes, int n_in,
                              void* d_out, int out_size) {
    const float* probs   = (const float*)d_in[0];
    const float* bbox    = (const float*)d_in[1];
    const float* anchors = (const float*)d_in[2];
    float* out = (float*)d_out;
    (void)in_sizes; (void)n_in; (void)out_size;

    dim3 gridN(128, BATCH);
    k_score_hist<<<gridN, 256>>>(probs);
    k_findbins<<<BATCH, 256>>>();
    dim3 gridC(64, BATCH);
    k_compact<<<gridC, 256>>>();
    k_select<<<BATCH, 256>>>();
    dim3 gridR(CAPW / 256, BATCH);
    k_rank<<<gridR, 256>>>(bbox, anchors);
    dim3 gridB(W / 64, W / 128, BATCH);
    k_build<<<gridB, 128>>>();
    k_nms_fast<<<BATCH, 32>>>(out);
    k_nms_exact<<<BATCH, 32>>>(out, bbox, anchors);
}